// round 14
// baseline (speedup 1.0000x reference)
#include <cuda_runtime.h>

// Problem constants (fixed by the reference setup_inputs)
#define NROWS   65536
#define DCOLS   1024
#define WARPS_PER_BLOCK 8
#define NBLOCKS (NROWS / WARPS_PER_BLOCK)   // 8192 blocks, 1 row per warp

#define RAD2DEG 57.29577951308232

// Deterministic per-block partials: [0..NBLOCKS) = sum(dot^2),
// [NBLOCKS..2N) = sum(x^2), [2N..3N) = sum(y^2). Fully overwritten every call.
__device__ __align__(16) float g_partials[NBLOCKS * 3];
__device__ unsigned int g_count = 0;   // arrival counter; reset by finalizer

__global__ __launch_bounds__(256, 4)
void ang_dif_kernel(const float* __restrict__ x,
                    const float* __restrict__ y,
                    float* __restrict__ out) {
    const int warp = threadIdx.x >> 5;
    const int lane = threadIdx.x & 31;
    const int row  = blockIdx.x * WARPS_PER_BLOCK + warp;

    // ── streaming body: EXACT R6/R11 loop measured at 6.87 TB/s ──
    const float4* __restrict__ xr =
        reinterpret_cast<const float4*>(x + (size_t)row * DCOLS);
    const float4* __restrict__ yr =
        reinterpret_cast<const float4*>(y + (size_t)row * DCOLS);

    float dot = 0.f, sx = 0.f, sy = 0.f;
    #pragma unroll
    for (int i = 0; i < 8; ++i) {
        float4 a = xr[lane + i * 32];
        float4 b = yr[lane + i * 32];
        dot = fmaf(a.x, b.x, dot); dot = fmaf(a.y, b.y, dot);
        dot = fmaf(a.z, b.z, dot); dot = fmaf(a.w, b.w, dot);
        sx  = fmaf(a.x, a.x, sx);  sx  = fmaf(a.y, a.y, sx);
        sx  = fmaf(a.z, a.z, sx);  sx  = fmaf(a.w, a.w, sx);
        sy  = fmaf(b.x, b.x, sy);  sy  = fmaf(b.y, b.y, sy);
        sy  = fmaf(b.z, b.z, sy);  sy  = fmaf(b.w, b.w, sy);
    }

    #pragma unroll
    for (int o = 16; o > 0; o >>= 1) {
        dot += __shfl_xor_sync(0xFFFFFFFFu, dot, o);
        sx  += __shfl_xor_sync(0xFFFFFFFFu, sx,  o);
        sy  += __shfl_xor_sync(0xFFFFFFFFu, sy,  o);
    }

    __shared__ float s[WARPS_PER_BLOCK][3];
    if (lane == 0) {
        s[warp][0] = dot * dot;   // per-row contribution is dot^2
        s[warp][1] = sx;
        s[warp][2] = sy;
    }
    __syncthreads();

    if (threadIdx.x < 3) {
        float acc = 0.f;
        #pragma unroll
        for (int w = 0; w < WARPS_PER_BLOCK; ++w) acc += s[w][threadIdx.x];
        g_partials[(size_t)threadIdx.x * NBLOCKS + blockIdx.x] = acc;
    }
    __syncthreads();   // CTA-scope ordering of all three partial stores

    // ── zero-stall arrival: red (no return, no wait), release scope gpu.
    //    The warp does NOT wait for completion; CTA exits immediately.
    if (threadIdx.x == 0) {
        asm volatile("red.release.gpu.global.add.u32 [%0], %1;"
                     :: "l"(&g_count), "r"(1u) : "memory");
    }

    if (blockIdx.x != 0) return;

    // ── block 0 = finalizer: spin until all 8192 arrivals, then reduce ──
    // No deadlock: block 0 holds 1 of 592 resident slots; the other 591
    // guarantee forward progress for all remaining CTAs.
    __shared__ int ready;
    if (threadIdx.x == 0) {
        unsigned int c;
        do {
            asm volatile("ld.acquire.gpu.global.u32 %0, [%1];"
                         : "=r"(c) : "l"(&g_count) : "memory");
            if (c < (unsigned int)NBLOCKS) __nanosleep(128);
        } while (c < (unsigned int)NBLOCKS);
        ready = 1;   // acquire above makes all partials visible
    }
    __syncthreads();
    (void)ready;

    // Reduce 3 x 8192 floats = 6144 float4 over 256 threads (24 float4 each),
    // L2-hot. Fixed order -> deterministic.
    const float4* __restrict__ p4 = reinterpret_cast<const float4*>(g_partials);
    float a0 = 0.f, a1 = 0.f, a2 = 0.f;
    for (int i = threadIdx.x; i < NBLOCKS / 4; i += 256) {
        float4 v0 = p4[i];        a0 += (v0.x + v0.y) + (v0.z + v0.w);
        float4 v1 = p4[i + 2048]; a1 += (v1.x + v1.y) + (v1.z + v1.w);
        float4 v2 = p4[i + 4096]; a2 += (v2.x + v2.y) + (v2.z + v2.w);
    }
    #pragma unroll
    for (int o = 16; o > 0; o >>= 1) {
        a0 += __shfl_xor_sync(0xFFFFFFFFu, a0, o);
        a1 += __shfl_xor_sync(0xFFFFFFFFu, a1, o);
        a2 += __shfl_xor_sync(0xFFFFFFFFu, a2, o);
    }

    __shared__ float f0[WARPS_PER_BLOCK], f1[WARPS_PER_BLOCK], f2[WARPS_PER_BLOCK];
    if (lane == 0) { f0[warp] = a0; f1[warp] = a1; f2[warp] = a2; }
    __syncthreads();

    if (threadIdx.x == 0) {
        double sum_dot2 = 0.0, sxx = 0.0, syy = 0.0;
        #pragma unroll
        for (int w = 0; w < WARPS_PER_BLOCK; ++w) {
            sum_dot2 += (double)f0[w];
            sxx      += (double)f1[w];
            syy      += (double)f2[w];
        }
        // mean((dot / (||x||*||y||) * RAD2DEG)^2)
        //   = RAD2DEG^2 * sum(dot^2) / (N * Sx * Sy)
        double r = (RAD2DEG * RAD2DEG) * sum_dot2 / (sxx * syy * (double)NROWS);
        out[0] = (float)r;
        g_count = 0;               // rearm for next graph replay
    }
}

extern "C" void kernel_launch(void* const* d_in, const int* in_sizes, int n_in,
                              void* d_out, int out_size) {
    const float* x = (const float*)d_in[0];
    const float* y = (const float*)d_in[1];
    float* out = (float*)d_out;

    ang_dif_kernel<<<NBLOCKS, 256>>>(x, y, out);
}

// round 15
// speedup vs baseline: 1.0479x; 1.0479x over previous
#include <cuda_runtime.h>

// Problem constants (fixed by the reference setup_inputs)
#define NROWS   65536
#define DCOLS   1024
#define WARPS_PER_BLOCK 8
#define NBLOCKS (NROWS / WARPS_PER_BLOCK)   // 8192 blocks, 1 row per warp

#define RAD2DEG 57.29577951308232

// Deterministic per-block partials: [0..NBLOCKS) = sum(dot^2),
// [NBLOCKS..2N) = sum(x^2), [2N..3N) = sum(y^2). Fully overwritten every call.
// 16B-aligned so the finalize kernel can read it as float4.
__device__ __align__(16) float g_partials[NBLOCKS * 3];

// ── Streaming kernel: R6/R11 body, occupancy raised 4 -> 6 CTAs/SM.
//    launch_bounds(256,6) caps regs at ~40, trading per-warp load batching
//    (~16 -> ~9 in flight) for +50% resident warps to fill DRAM idle cycles
//    (measured dram__cycles_active was only 79-80% at occ 4).
__global__ __launch_bounds__(256, 6)
void rowdot_kernel(const float* __restrict__ x, const float* __restrict__ y) {
    const int warp = threadIdx.x >> 5;
    const int lane = threadIdx.x & 31;
    const int row  = blockIdx.x * WARPS_PER_BLOCK + warp;

    const float4* __restrict__ xr =
        reinterpret_cast<const float4*>(x + (size_t)row * DCOLS);
    const float4* __restrict__ yr =
        reinterpret_cast<const float4*>(y + (size_t)row * DCOLS);

    float dot = 0.f, sx = 0.f, sy = 0.f;
    // 1024 floats / row = 256 float4; 32 lanes -> 8 iters, fully coalesced.
    #pragma unroll
    for (int i = 0; i < 8; ++i) {
        float4 a = xr[lane + i * 32];
        float4 b = yr[lane + i * 32];
        dot = fmaf(a.x, b.x, dot); dot = fmaf(a.y, b.y, dot);
        dot = fmaf(a.z, b.z, dot); dot = fmaf(a.w, b.w, dot);
        sx  = fmaf(a.x, a.x, sx);  sx  = fmaf(a.y, a.y, sx);
        sx  = fmaf(a.z, a.z, sx);  sx  = fmaf(a.w, a.w, sx);
        sy  = fmaf(b.x, b.x, sy);  sy  = fmaf(b.y, b.y, sy);
        sy  = fmaf(b.z, b.z, sy);  sy  = fmaf(b.w, b.w, sy);
    }

    // Warp tree reduce (deterministic order)
    #pragma unroll
    for (int o = 16; o > 0; o >>= 1) {
        dot += __shfl_xor_sync(0xFFFFFFFFu, dot, o);
        sx  += __shfl_xor_sync(0xFFFFFFFFu, sx,  o);
        sy  += __shfl_xor_sync(0xFFFFFFFFu, sy,  o);
    }

    __shared__ float s[WARPS_PER_BLOCK][3];
    if (lane == 0) {
        s[warp][0] = dot * dot;   // per-row contribution is dot^2
        s[warp][1] = sx;
        s[warp][2] = sy;
    }
    __syncthreads();

    if (threadIdx.x < 3) {
        float acc = 0.f;
        #pragma unroll
        for (int w = 0; w < WARPS_PER_BLOCK; ++w) acc += s[w][threadIdx.x];
        g_partials[(size_t)threadIdx.x * NBLOCKS + blockIdx.x] = acc;
    }
}

// ── Finalize: vectorized (6 independent LDG.128/thread over 96 KB L2-hot).
//    5.6 us measured, dominated by fixed launch overhead — left unchanged.
__global__ __launch_bounds__(1024)
void finalize_kernel(float* __restrict__ out) {
    const int tid  = threadIdx.x;
    const int warp = tid >> 5;
    const int lane = tid & 31;

    // Each section is NBLOCKS floats = 2048 float4. 1024 threads -> 2 each.
    const float4* __restrict__ p4 = reinterpret_cast<const float4*>(g_partials);

    float4 v00 = p4[tid];                 // dot^2 section
    float4 v01 = p4[tid + 1024];
    float4 v10 = p4[2048 + tid];          // sum x^2 section
    float4 v11 = p4[2048 + tid + 1024];
    float4 v20 = p4[4096 + tid];          // sum y^2 section
    float4 v21 = p4[4096 + tid + 1024];

    float a0 = ((v00.x + v00.y) + (v00.z + v00.w))
             + ((v01.x + v01.y) + (v01.z + v01.w));
    float a1 = ((v10.x + v10.y) + (v10.z + v10.w))
             + ((v11.x + v11.y) + (v11.z + v11.w));
    float a2 = ((v20.x + v20.y) + (v20.z + v20.w))
             + ((v21.x + v21.y) + (v21.z + v21.w));

    #pragma unroll
    for (int o = 16; o > 0; o >>= 1) {
        a0 += __shfl_xor_sync(0xFFFFFFFFu, a0, o);
        a1 += __shfl_xor_sync(0xFFFFFFFFu, a1, o);
        a2 += __shfl_xor_sync(0xFFFFFFFFu, a2, o);
    }

    __shared__ float s0[32], s1[32], s2[32];
    if (lane == 0) { s0[warp] = a0; s1[warp] = a1; s2[warp] = a2; }
    __syncthreads();

    if (warp == 0) {
        float v0 = s0[lane], v1 = s1[lane], v2 = s2[lane];
        #pragma unroll
        for (int o = 16; o > 0; o >>= 1) {
            v0 += __shfl_xor_sync(0xFFFFFFFFu, v0, o);
            v1 += __shfl_xor_sync(0xFFFFFFFFu, v1, o);
            v2 += __shfl_xor_sync(0xFFFFFFFFu, v2, o);
        }
        if (lane == 0) {
            // mean((dot / (||x||*||y||) * RAD2DEG)^2)
            //   = RAD2DEG^2 * sum(dot^2) / (N * Sx * Sy)
            double sum_dot2 = (double)v0;
            double sxx = (double)v1;
            double syy = (double)v2;
            double r = (RAD2DEG * RAD2DEG) * sum_dot2 / (sxx * syy * (double)NROWS);
            out[0] = (float)r;
        }
    }
}

extern "C" void kernel_launch(void* const* d_in, const int* in_sizes, int n_in,
                              void* d_out, int out_size) {
    const float* x = (const float*)d_in[0];
    const float* y = (const float*)d_in[1];
    float* out = (float*)d_out;

    rowdot_kernel<<<NBLOCKS, 256>>>(x, y);
    finalize_kernel<<<1, 1024>>>(out);
}

// round 16
// speedup vs baseline: 1.0764x; 1.0272x over previous
#include <cuda_runtime.h>

// Problem constants (fixed by the reference setup_inputs)
#define NROWS   65536
#define DCOLS   1024
#define WARPS_PER_BLOCK 8
#define NBLOCKS (NROWS / WARPS_PER_BLOCK)   // 8192 blocks, 1 row per warp

#define RAD2DEG 57.29577951308232

// Deterministic per-block partials: [0..NBLOCKS) = sum(dot^2),
// [NBLOCKS..2N) = sum(x^2), [2N..3N) = sum(y^2). Fully overwritten every call.
// 16B-aligned so the finalize kernel can read it as float4.
__device__ __align__(16) float g_partials[NBLOCKS * 3];

// ── Streaming kernel: EXACT R11 occ-4 body (74.6 us, 6.87 TB/s measured —
//    best of occ-4/occ-6/persistent/fused x2). Only addition: a PDL trigger
//    after the partial store so the finalize kernel's launch overhead
//    overlaps the tail wave.
__global__ __launch_bounds__(256, 4)
void rowdot_kernel(const float* __restrict__ x, const float* __restrict__ y) {
    const int warp = threadIdx.x >> 5;
    const int lane = threadIdx.x & 31;
    const int row  = blockIdx.x * WARPS_PER_BLOCK + warp;

    const float4* __restrict__ xr =
        reinterpret_cast<const float4*>(x + (size_t)row * DCOLS);
    const float4* __restrict__ yr =
        reinterpret_cast<const float4*>(y + (size_t)row * DCOLS);

    float dot = 0.f, sx = 0.f, sy = 0.f;
    // 1024 floats / row = 256 float4; 32 lanes -> 8 iters, fully coalesced.
    #pragma unroll
    for (int i = 0; i < 8; ++i) {
        float4 a = xr[lane + i * 32];
        float4 b = yr[lane + i * 32];
        dot = fmaf(a.x, b.x, dot); dot = fmaf(a.y, b.y, dot);
        dot = fmaf(a.z, b.z, dot); dot = fmaf(a.w, b.w, dot);
        sx  = fmaf(a.x, a.x, sx);  sx  = fmaf(a.y, a.y, sx);
        sx  = fmaf(a.z, a.z, sx);  sx  = fmaf(a.w, a.w, sx);
        sy  = fmaf(b.x, b.x, sy);  sy  = fmaf(b.y, b.y, sy);
        sy  = fmaf(b.z, b.z, sy);  sy  = fmaf(b.w, b.w, sy);
    }

    // Warp tree reduce (deterministic order)
    #pragma unroll
    for (int o = 16; o > 0; o >>= 1) {
        dot += __shfl_xor_sync(0xFFFFFFFFu, dot, o);
        sx  += __shfl_xor_sync(0xFFFFFFFFu, sx,  o);
        sy  += __shfl_xor_sync(0xFFFFFFFFu, sy,  o);
    }

    __shared__ float s[WARPS_PER_BLOCK][3];
    if (lane == 0) {
        s[warp][0] = dot * dot;   // per-row contribution is dot^2
        s[warp][1] = sx;
        s[warp][2] = sy;
    }
    __syncthreads();

    if (threadIdx.x < 3) {
        float acc = 0.f;
        #pragma unroll
        for (int w = 0; w < WARPS_PER_BLOCK; ++w) acc += s[w][threadIdx.x];
        g_partials[(size_t)threadIdx.x * NBLOCKS + blockIdx.x] = acc;
    }

    // PDL: allow the dependent finalize kernel to begin launching. Fires when
    // all CTAs have executed this (i.e., as the last wave drains). Memory
    // visibility is enforced by the consumer's cudaGridDependencySynchronize.
    cudaTriggerProgrammaticLaunchCompletion();
}

// ── Finalize: vectorized reduce of 96 KB L2-hot partials. Launched with
//    programmatic stream serialization so its launch overhead overlaps the
//    primary's tail; the grid-dependency sync below provides correctness.
__global__ __launch_bounds__(1024)
void finalize_kernel(float* __restrict__ out) {
    const int tid  = threadIdx.x;
    const int warp = tid >> 5;
    const int lane = tid & 31;

    // Block until the primary grid has fully completed and its memory
    // (g_partials) is visible.
    cudaGridDependencySynchronize();

    // Each section is NBLOCKS floats = 2048 float4. 1024 threads -> 2 each.
    const float4* __restrict__ p4 = reinterpret_cast<const float4*>(g_partials);

    float4 v00 = p4[tid];                 // dot^2 section
    float4 v01 = p4[tid + 1024];
    float4 v10 = p4[2048 + tid];          // sum x^2 section
    float4 v11 = p4[2048 + tid + 1024];
    float4 v20 = p4[4096 + tid];          // sum y^2 section
    float4 v21 = p4[4096 + tid + 1024];

    float a0 = ((v00.x + v00.y) + (v00.z + v00.w))
             + ((v01.x + v01.y) + (v01.z + v01.w));
    float a1 = ((v10.x + v10.y) + (v10.z + v10.w))
             + ((v11.x + v11.y) + (v11.z + v11.w));
    float a2 = ((v20.x + v20.y) + (v20.z + v20.w))
             + ((v21.x + v21.y) + (v21.z + v21.w));

    #pragma unroll
    for (int o = 16; o > 0; o >>= 1) {
        a0 += __shfl_xor_sync(0xFFFFFFFFu, a0, o);
        a1 += __shfl_xor_sync(0xFFFFFFFFu, a1, o);
        a2 += __shfl_xor_sync(0xFFFFFFFFu, a2, o);
    }

    __shared__ float s0[32], s1[32], s2[32];
    if (lane == 0) { s0[warp] = a0; s1[warp] = a1; s2[warp] = a2; }
    __syncthreads();

    if (warp == 0) {
        float v0 = s0[lane], v1 = s1[lane], v2 = s2[lane];
        #pragma unroll
        for (int o = 16; o > 0; o >>= 1) {
            v0 += __shfl_xor_sync(0xFFFFFFFFu, v0, o);
            v1 += __shfl_xor_sync(0xFFFFFFFFu, v1, o);
            v2 += __shfl_xor_sync(0xFFFFFFFFu, v2, o);
        }
        if (lane == 0) {
            // mean((dot / (||x||*||y||) * RAD2DEG)^2)
            //   = RAD2DEG^2 * sum(dot^2) / (N * Sx * Sy)
            double sum_dot2 = (double)v0;
            double sxx = (double)v1;
            double syy = (double)v2;
            double r = (RAD2DEG * RAD2DEG) * sum_dot2 / (sxx * syy * (double)NROWS);
            out[0] = (float)r;
        }
    }
}

extern "C" void kernel_launch(void* const* d_in, const int* in_sizes, int n_in,
                              void* d_out, int out_size) {
    const float* x = (const float*)d_in[0];
    const float* y = (const float*)d_in[1];
    float* out = (float*)d_out;

    rowdot_kernel<<<NBLOCKS, 256>>>(x, y);

    // Launch finalize with Programmatic Dependent Launch so its setup
    // overlaps the primary's tail wave (same stream; graph-capturable).
    cudaLaunchConfig_t cfg = {};
    cfg.gridDim  = dim3(1, 1, 1);
    cfg.blockDim = dim3(1024, 1, 1);
    cfg.dynamicSmemBytes = 0;
    cfg.stream = 0;   // same (captured) default stream as the primary
    cudaLaunchAttribute attr[1];
    attr[0].id = cudaLaunchAttributeProgrammaticStreamSerialization;
    attr[0].val.programmaticStreamSerializationAllowed = 1;
    cfg.attrs = attr;
    cfg.numAttrs = 1;
    cudaLaunchKernelEx(&cfg, finalize_kernel, out);
}